// round 1
// baseline (speedup 1.0000x reference)
#include <cuda_runtime.h>
#include <cstdint>

// Problem constants (fixed by the registry problem)
#define BATCH 32
#define NBR   8
#define BDIM  256          // B = BATCH*NBR
#define LDIM  64
#define KDIM  8
#define UDIM  4
#define DIN   64           // 2*K*U
#define HDIM  512
#define CDIM  1024         // 2*h
#define MOUT  144          // layer-2 output channels (2*(2KU+K))
#define BL    16384        // B*L
#define NS_STRIDE ((size_t)BL * HDIM)   // per-sample stride in noise arrays
#define OUT_FRE  0
#define OUT_FIM  524288
#define OUT_I    1048576

// ---------------- scratch (device globals; no allocation allowed) ----------------
__device__ float g_A0[LDIM * DIN * BDIM];        //  4 MB  [n][d][b]
__device__ float g_Y [LDIM * CDIM * BDIM];       // 64 MB  [n][o][b]
__device__ float g_A [LDIM * HDIM * BDIM];       // 32 MB  [n][d][b]
__device__ float g_M [BL * HDIM];                // 32 MB  [bl][h]
__device__ float g_S [BL * HDIM];                // 32 MB  [bl][h]
__device__ float g_Y2[LDIM * MOUT * BDIM];       //  9 MB  [n][c][b]
__device__ float g_scale[CDIM];
__device__ float g_shift[CDIM];
__device__ float g_Pn[BDIM * KDIM];
__device__ float g_Ipart[BL];

// ---------------- f32x2 helpers (packed dual-FMA = full-rate fp32 on B300) -------
__device__ __forceinline__ unsigned long long pk2(float lo, float hi) {
    unsigned long long r;
    asm("mov.b64 %0, {%1, %2};" : "=l"(r) : "f"(lo), "f"(hi));
    return r;
}
__device__ __forceinline__ void fma2(unsigned long long& acc, unsigned long long a,
                                     unsigned long long b) {
    asm("fma.rn.f32x2 %0, %1, %2, %0;" : "+l"(acc) : "l"(a), "l"(b));
}
__device__ __forceinline__ void unpk2(unsigned long long v, float& lo, float& hi) {
    asm("mov.b64 {%0, %1}, %2;" : "=f"(lo), "=f"(hi) : "l"(v));
}

// ---------------- build A0: [n][d][b], d<32 from Hre, else Him -------------------
__global__ void build_a0(const float* __restrict__ Hre, const float* __restrict__ Him) {
    int n = blockIdx.x, b = threadIdx.x;
    size_t hbase = ((size_t)b * LDIM + n) * 32;
#pragma unroll
    for (int d = 0; d < DIN; d++) {
        float v = (d < 32) ? Hre[hbase + d] : Him[hbase + d - 32];
        g_A0[((size_t)n * DIN + d) * BDIM + b] = v;
    }
}

// ---------------- batched SGEMM: Y[n][o][b] = sum_d P[n][o][d] * A[n][d][b] ------
// grid: (M/BM, 256/BN, 64), block: (BN/TN, BM/TM)
template <int BM, int BN, int BK, int TM, int TN, bool RELU>
__global__ __launch_bounds__(256) void gemm_kernel(
    const float* __restrict__ P, const float* __restrict__ A, float* __restrict__ Y,
    int M, int Kd)
{
    constexpr int TX = BN / TN;
    constexpr int TY = BM / TM;
    static_assert(TX * TY == 256, "need 256 threads");
    __shared__ __align__(16) float As[BK][BM + 4];
    __shared__ __align__(16) float Bs[BK][BN];

    const int n  = blockIdx.z;
    const int m0 = blockIdx.x * BM;
    const int n0 = blockIdx.y * BN;
    const float* Pg = P + (size_t)n * M * Kd;
    const float* Ag = A + (size_t)n * Kd * BDIM;
    float*       Yg = Y + (size_t)n * M * BDIM;

    const int tx = threadIdx.x, ty = threadIdx.y;
    const int tid = ty * TX + tx;

    unsigned long long acc[TM][TN / 2];
#pragma unroll
    for (int i = 0; i < TM; i++)
#pragma unroll
        for (int j = 0; j < TN / 2; j++) acc[i][j] = 0ull;

    for (int k0 = 0; k0 < Kd; k0 += BK) {
        // load P tile (transposed into As[k][m]); coalesced over kk
#pragma unroll
        for (int i = tid; i < BM * BK; i += 256) {
            int m = i / BK, kk = i % BK;
            As[kk][m] = Pg[(size_t)(m0 + m) * Kd + k0 + kk];
        }
        // load A tile (direct, float4)
#pragma unroll
        for (int i = tid; i < BK * BN / 4; i += 256) {
            int kk = i / (BN / 4), nn = (i % (BN / 4)) * 4;
            *(float4*)&Bs[kk][nn] =
                *(const float4*)&Ag[(size_t)(k0 + kk) * BDIM + n0 + nn];
        }
        __syncthreads();

#pragma unroll
        for (int kk = 0; kk < BK; kk++) {
            float a[TM], b[TN];
#pragma unroll
            for (int i = 0; i < TM; i += 4)
                *(float4*)&a[i] = *(const float4*)&As[kk][ty * TM + i];
#pragma unroll
            for (int j = 0; j < TN; j += 4)
                *(float4*)&b[j] = *(const float4*)&Bs[kk][tx * TN + j];
            unsigned long long b2[TN / 2];
#pragma unroll
            for (int j = 0; j < TN / 2; j++) b2[j] = pk2(b[2 * j], b[2 * j + 1]);
#pragma unroll
            for (int i = 0; i < TM; i++) {
                unsigned long long a2 = pk2(a[i], a[i]);
#pragma unroll
                for (int j = 0; j < TN / 2; j++) fma2(acc[i][j], a2, b2[j]);
            }
        }
        __syncthreads();
    }

#pragma unroll
    for (int i = 0; i < TM; i++) {
        int row = m0 + ty * TM + i;
#pragma unroll
        for (int j = 0; j < TN / 2; j++) {
            float lo, hi;
            unpk2(acc[i][j], lo, hi);
            if (RELU) { lo = fmaxf(lo, 0.f); hi = fmaxf(hi, 0.f); }
            float2 v = make_float2(lo, hi);
            *(float2*)&Yg[(size_t)row * BDIM + n0 + tx * TN + 2 * j] = v;
        }
    }
}

// ---------------- BN stats per channel o (reduce over n,b) -----------------------
__global__ void bn_stats(const float* __restrict__ Y, const float* __restrict__ w,
                         const float* __restrict__ bb) {
    int o = blockIdx.x, t = threadIdx.x;
    double s = 0.0, s2 = 0.0;
#pragma unroll
    for (int n = 0; n < LDIM; n++) {
        float v = Y[((size_t)n * CDIM + o) * BDIM + t];
        s += v;
        s2 += (double)v * v;
    }
    __shared__ double sh[256], sh2[256];
    sh[t] = s; sh2[t] = s2;
    __syncthreads();
    for (int off = 128; off; off >>= 1) {
        if (t < off) { sh[t] += sh[t + off]; sh2[t] += sh2[t + off]; }
        __syncthreads();
    }
    if (t == 0) {
        double mean = sh[0] / (double)BL;
        double var  = sh2[0] / (double)BL - mean * mean;
        float sc = w[o] * rsqrtf((float)var + 1e-5f);
        g_scale[o] = sc;
        g_shift[o] = bb[o] - (float)mean * sc;
    }
}

// ---------------- BN apply: A[n][d][b] + transposed M/S buffers [bl][h] ----------
// grid (64, 16, 8): (n, d-tile of 32 within [0,512), b-tile of 32); block (32,8)
__global__ void bn_apply(const float* __restrict__ Y) {
    int n = blockIdx.x, d0 = blockIdx.y * 32, b0 = blockIdx.z * 32;
    __shared__ float tm[32][33], ts[32][33];
    int tx = threadIdx.x, ty = threadIdx.y;
#pragma unroll
    for (int r = 0; r < 4; r++) {
        int dd = r * 8 + ty;
        int d = d0 + dd, b = b0 + tx;
        float m = g_scale[d] * Y[((size_t)n * CDIM + d) * BDIM + b] + g_shift[d];
        g_A[((size_t)n * HDIM + d) * BDIM + b] = m;
        tm[dd][tx] = m;
        int ds = d + HDIM;
        float x = g_scale[ds] * Y[((size_t)n * CDIM + ds) * BDIM + b] + g_shift[ds];
        float sp = fmaxf(x, 0.f) + log1pf(expf(-fabsf(x)));  // softplus (logaddexp)
        ts[dd][tx] = sp + 1e-10f;
    }
    __syncthreads();
#pragma unroll
    for (int r = 0; r < 4; r++) {
        int bb = r * 8 + ty;
        size_t bl = (size_t)(b0 + bb) * LDIM + n;
        g_M[bl * HDIM + d0 + tx] = tm[tx][bb];
        g_S[bl * HDIM + d0 + tx] = ts[tx][bb];
    }
}

// ---------------- noise/MI pass: stream noise once, closed-form in S1,S2 --------
// mean_s(z_logit - p_logit) per (bl,h) = 0.5 m^2 - log s + m s S1 + 0.5 (s^2-1) S2
__global__ void noise_kernel(const float* __restrict__ Nz, int add) {
    int bl = blockIdx.x, t = threadIdx.x;
    float local = 0.f;
#pragma unroll
    for (int h = t; h < HDIM; h += 256) {
        size_t idx = (size_t)bl * HDIM + h;
        float m = g_M[idx], s = g_S[idx];
        float n0 = Nz[idx];
        float n1 = Nz[idx + NS_STRIDE];
        float n2 = Nz[idx + 2 * NS_STRIDE];
        float n3 = Nz[idx + 3 * NS_STRIDE];
        float S1 = (n0 + n1 + n2 + n3) * 0.25f;
        float S2 = (n0 * n0 + n1 * n1 + n2 * n2 + n3 * n3) * 0.25f;
        local += 0.5f * m * m - logf(s) + m * s * S1 + 0.5f * (s * s - 1.0f) * S2;
    }
    __shared__ float sh[256];
    sh[t] = local;
    __syncthreads();
    for (int off = 128; off; off >>= 1) {
        if (t < off) sh[t] += sh[t + off];
        __syncthreads();
    }
    if (t == 0) {
        if (add) g_Ipart[bl] += sh[0];
        else     g_Ipart[bl]  = sh[0];
    }
}

// ---------------- Pn[b][k] = || Y2[:,64+k,b] ||_n -------------------------------
__global__ void pn_kernel() {
    int k = blockIdx.x, b = threadIdx.x;
    float s = 0.f;
#pragma unroll
    for (int n = 0; n < LDIM; n++) {
        float v = g_Y2[((size_t)n * MOUT + 64 + k) * BDIM + b];
        s += v * v;
    }
    g_Pn[b * KDIM + k] = sqrtf(s);
}

// ---------------- final: normalize F, scale by Pu, write Fre/Fim ----------------
__global__ void final_kernel(float* __restrict__ out) {
    int n = blockIdx.x, b = threadIdx.x;
    float v[72];
#pragma unroll
    for (int c = 0; c < 72; c++) v[c] = g_Y2[((size_t)n * MOUT + c) * BDIM + b];
    size_t obase = ((size_t)b * LDIM + n) * 32;
#pragma unroll
    for (int k = 0; k < KDIM; k++) {
        float ss = 0.f;
#pragma unroll
        for (int u = 0; u < UDIM; u++) {
            float a = v[k * 4 + u], c = v[32 + k * 4 + u];
            ss += a * a + c * c;
        }
        float f3 = sqrtf(ss);
        float pu = v[64 + k] / g_Pn[b * KDIM + k] * 8.0f;  // sqrt(L)=8
        float mult = pu / f3;
#pragma unroll
        for (int u = 0; u < UDIM; u++) {
            out[OUT_FRE + obase + k * 4 + u] = v[k * 4 + u] * mult;
            out[OUT_FIM + obase + k * 4 + u] = v[32 + k * 4 + u] * mult;
        }
    }
}

// ---------------- I[b] = sum_n Ipart[b*64+n] ------------------------------------
__global__ void write_i(float* __restrict__ out) {
    int b = threadIdx.x;
    float s = 0.f;
#pragma unroll
    for (int n = 0; n < LDIM; n++) s += g_Ipart[b * LDIM + n];
    out[OUT_I + b] = s;
}

// ---------------- launch --------------------------------------------------------
extern "C" void kernel_launch(void* const* d_in, const int* in_sizes, int n_in,
                              void* d_out, int out_size) {
    const float* Hre = (const float*)d_in[0];
    const float* Him = (const float*)d_in[1];
    const float* P0  = (const float*)d_in[2];
    const float* P1  = (const float*)d_in[3];
    const float* P2  = (const float*)d_in[4];
    const float* w0  = (const float*)d_in[5];
    const float* b0  = (const float*)d_in[6];
    const float* w1  = (const float*)d_in[7];
    const float* b1  = (const float*)d_in[8];
    const float* nz0 = (const float*)d_in[9];
    const float* nz1 = (const float*)d_in[10];
    float* out = (float*)d_out;

    float *A0p, *Yp, *Ap, *Y2p;
    cudaGetSymbolAddress((void**)&A0p, g_A0);
    cudaGetSymbolAddress((void**)&Yp,  g_Y);
    cudaGetSymbolAddress((void**)&Ap,  g_A);
    cudaGetSymbolAddress((void**)&Y2p, g_Y2);

    // layer 0
    build_a0<<<LDIM, BDIM>>>(Hre, Him);
    gemm_kernel<128, 128, 16, 8, 8, true>
        <<<dim3(8, 2, LDIM), dim3(16, 16)>>>(P0, A0p, Yp, CDIM, DIN);
    bn_stats<<<CDIM, 256>>>(Yp, w0, b0);
    bn_apply<<<dim3(LDIM, 16, 8), dim3(32, 8)>>>(Yp);
    noise_kernel<<<BL, 256>>>(nz0, 0);

    // layer 1
    gemm_kernel<128, 128, 16, 8, 8, true>
        <<<dim3(8, 2, LDIM), dim3(16, 16)>>>(P1, Ap, Yp, CDIM, HDIM);
    bn_stats<<<CDIM, 256>>>(Yp, w1, b1);
    bn_apply<<<dim3(LDIM, 16, 8), dim3(32, 8)>>>(Yp);
    noise_kernel<<<BL, 256>>>(nz1, 1);

    // layer 2 (no act/bn)
    gemm_kernel<16, 256, 16, 4, 4, false>
        <<<dim3(9, 1, LDIM), dim3(64, 4)>>>(P2, Ap, Y2p, MOUT, HDIM);

    // epilogue
    pn_kernel<<<KDIM, BDIM>>>();
    final_kernel<<<LDIM, BDIM>>>(out);
    write_i<<<1, BDIM>>>(out);
}

// round 4
// speedup vs baseline: 2.1209x; 2.1209x over previous
#include <cuda_runtime.h>
#include <cuda_bf16.h>
#include <cstdint>

// Problem constants
#define BDIM  256          // B = BATCH*NBR
#define LDIM  64
#define DIN   64           // 2*K*U
#define HDIM  512
#define CDIM  1024         // 2*h
#define MOUT  144
#define BL    16384        // B*L
#define NS_STRIDE ((size_t)BL * HDIM)
#define OUT_FRE  0
#define OUT_FIM  524288
#define OUT_I    1048576

// ---------------- scratch ----------------
__device__ __align__(128) float g_A0[BDIM * LDIM * DIN];     //  4 MB [b][n][d]
__device__ __align__(128) float g_Y [LDIM * BDIM * CDIM];    // 64 MB [n][b][o]
__device__ __align__(128) float g_M [BL * HDIM];             // 32 MB [b*64+n][h]
__device__ __align__(128) float g_S [BL * HDIM];             // 32 MB
__device__ __align__(128) float g_Y2[LDIM * BDIM * MOUT];    //  9 MB [n][b][c]
__device__ float g_pS [64 * CDIM];
__device__ float g_pS2[64 * CDIM];
__device__ float g_scale[CDIM];
__device__ float g_shift[CDIM];
__device__ float g_Pn[BDIM * 8];
__device__ float g_Ipart[BL];

// ================= helpers =================
__device__ __forceinline__ uint32_t smem_u32(const void* p) {
    uint32_t a;
    asm("{ .reg .u64 t; cvta.to.shared.u64 t, %1; cvt.u32.u64 %0, t; }" : "=r"(a) : "l"(p));
    return a;
}
__device__ __forceinline__ void ldmx4(uint32_t* r, uint32_t addr) {
    asm volatile("ldmatrix.sync.aligned.m8n8.x4.shared.b16 {%0,%1,%2,%3}, [%4];"
        : "=r"(r[0]), "=r"(r[1]), "=r"(r[2]), "=r"(r[3]) : "r"(addr));
}
__device__ __forceinline__ void mma_bf16(float* c, const uint32_t* a,
                                         uint32_t b0, uint32_t b1) {
    asm volatile("mma.sync.aligned.m16n8k16.row.col.f32.bf16.bf16.f32 "
        "{%0,%1,%2,%3}, {%4,%5,%6,%7}, {%8,%9}, {%0,%1,%2,%3};"
        : "+f"(c[0]), "+f"(c[1]), "+f"(c[2]), "+f"(c[3])
        : "r"(a[0]), "r"(a[1]), "r"(a[2]), "r"(a[3]), "r"(b0), "r"(b1));
}
__device__ __forceinline__ uint32_t bf2u(__nv_bfloat162 h) {
    return *reinterpret_cast<uint32_t*>(&h);
}
__device__ __forceinline__ void cvt_hilo(float4 v, uint2& hi, uint2& lo) {
    __nv_bfloat162 h01 = __floats2bfloat162_rn(v.x, v.y);
    __nv_bfloat162 h23 = __floats2bfloat162_rn(v.z, v.w);
    float2 f01 = __bfloat1622float2(h01);
    float2 f23 = __bfloat1622float2(h23);
    __nv_bfloat162 l01 = __floats2bfloat162_rn(v.x - f01.x, v.y - f01.y);
    __nv_bfloat162 l23 = __floats2bfloat162_rn(v.z - f23.x, v.w - f23.y);
    hi.x = bf2u(h01); hi.y = bf2u(h23);
    lo.x = bf2u(l01); lo.y = bf2u(l23);
}

// ================= tensor-core batched GEMM (mma.sync bf16 3-term) =================
// Y[n][b][o] = sum_d P[n][o][d] * Act[(b*64+n)][d]
// CTA tile: 128 b x 128 o x 64 k; 8 warps (2 b x 4 o), warp tile 64x32.
// smem per buffer: AH(act hi) 16K | AL 16K | BH(P hi) 16K | BL 16K ; double buffered.
#define GBUF 65536
#define GSMEM (2 * GBUF)

__global__ __launch_bounds__(256) void gemm_mma(
    const float* __restrict__ Pw, const float* __restrict__ Act,
    float* __restrict__ Y, int K, int M, int relu)
{
    extern __shared__ char sm[];
    const int tid = threadIdx.x, wid = tid >> 5, lid = tid & 31;
    const int m0 = blockIdx.x * 128, b0 = blockIdx.y * 128, n = blockIdx.z;
    const int nchunk = K >> 6;
    uint32_t sb = smem_u32(sm);

    // global-load indexing: thread covers (row = j*16 + r0, float4 col c4)
    const int r0 = tid >> 4, c4 = tid & 15;
    // swizzled within-row byte offset for the 8B (4xbf16) piece
    const int csw = (((c4 >> 1) ^ (r0 & 7)) << 4) + (c4 & 1) * 8;

    // ldmatrix lane geometry
    const int lr  = (lid & 7) + ((lid >> 3) & 1) * 8;   // row within 16
    const int kch = lid >> 4;                           // k-chunk half (0/1)
    const int warp_b = wid >> 2, warp_o = wid & 3;
    int rowA128[4], r7A[4], rowB128[2], r7B[2];
#pragma unroll
    for (int mm = 0; mm < 4; mm++) {
        int r = warp_b * 64 + mm * 16 + lr;
        rowA128[mm] = r * 128; r7A[mm] = r & 7;
    }
#pragma unroll
    for (int g = 0; g < 2; g++) {
        int r = warp_o * 32 + g * 16 + lr;
        rowB128[g] = r * 128; r7B[g] = r & 7;
    }

    float acc[4][4][4];
#pragma unroll
    for (int i = 0; i < 4; i++)
#pragma unroll
        for (int j = 0; j < 4; j++)
#pragma unroll
            for (int q = 0; q < 4; q++) acc[i][j][q] = 0.f;

    float4 stA[8], stP[8];

    // ---- prologue: load chunk 0 ----
#pragma unroll
    for (int j = 0; j < 8; j++) {
        int row = j * 16 + r0;
        stA[j] = *(const float4*)&Act[((size_t)(b0 + row) * 64 + n) * K + c4 * 4];
        if (m0 + row < M)
            stP[j] = *(const float4*)&Pw[((size_t)n * M + m0 + row) * K + c4 * 4];
        else stP[j] = make_float4(0.f, 0.f, 0.f, 0.f);
    }
    {
        char* buf = sm;
#pragma unroll
        for (int j = 0; j < 8; j++) {
            int off = (j * 16 + r0) * 128 + csw;
            uint2 hi, lo;
            cvt_hilo(stA[j], hi, lo);
            *(uint2*)(buf + off) = hi;
            *(uint2*)(buf + 16384 + off) = lo;
            cvt_hilo(stP[j], hi, lo);
            *(uint2*)(buf + 32768 + off) = hi;
            *(uint2*)(buf + 49152 + off) = lo;
        }
    }
    __syncthreads();

    for (int c = 0; c < nchunk; c++) {
        // issue next chunk's global loads early (latency hidden by MMA below)
        if (c + 1 < nchunk) {
            int k0 = (c + 1) << 6;
#pragma unroll
            for (int j = 0; j < 8; j++) {
                int row = j * 16 + r0;
                stA[j] = *(const float4*)&Act[((size_t)(b0 + row) * 64 + n) * K + k0 + c4 * 4];
                if (m0 + row < M)
                    stP[j] = *(const float4*)&Pw[((size_t)n * M + m0 + row) * K + k0 + c4 * 4];
                else stP[j] = make_float4(0.f, 0.f, 0.f, 0.f);
            }
        }

        // ---- compute on buffer c&1 ----
        uint32_t ub = sb + (c & 1) * GBUF;
#pragma unroll
        for (int kk = 0; kk < 4; kk++) {
            uint32_t ah[4][4], al[4][4], bh[2][4], bl2[2][4];
            int ksel = kk * 2 + kch;
#pragma unroll
            for (int mm = 0; mm < 4; mm++)
                ldmx4(ah[mm], ub + rowA128[mm] + ((ksel ^ r7A[mm]) << 4));
#pragma unroll
            for (int mm = 0; mm < 4; mm++)
                ldmx4(al[mm], ub + 16384 + rowA128[mm] + ((ksel ^ r7A[mm]) << 4));
#pragma unroll
            for (int g = 0; g < 2; g++)
                ldmx4(bh[g], ub + 32768 + rowB128[g] + ((ksel ^ r7B[g]) << 4));
#pragma unroll
            for (int g = 0; g < 2; g++)
                ldmx4(bl2[g], ub + 49152 + rowB128[g] + ((ksel ^ r7B[g]) << 4));
#pragma unroll
            for (int mm = 0; mm < 4; mm++)
#pragma unroll
                for (int nn = 0; nn < 4; nn++) {
                    int g = nn >> 1, s = nn & 1;
                    mma_bf16(acc[mm][nn], ah[mm], bh[g][s],  bh[g][s + 2]);
                    mma_bf16(acc[mm][nn], ah[mm], bl2[g][s], bl2[g][s + 2]);
                    mma_bf16(acc[mm][nn], al[mm], bh[g][s],  bh[g][s + 2]);
                }
        }

        // ---- store next chunk into other buffer ----
        if (c + 1 < nchunk) {
            char* buf = sm + ((c + 1) & 1) * GBUF;
#pragma unroll
            for (int j = 0; j < 8; j++) {
                int off = (j * 16 + r0) * 128 + csw;
                uint2 hi, lo;
                cvt_hilo(stA[j], hi, lo);
                *(uint2*)(buf + off) = hi;
                *(uint2*)(buf + 16384 + off) = lo;
                cvt_hilo(stP[j], hi, lo);
                *(uint2*)(buf + 32768 + off) = hi;
                *(uint2*)(buf + 49152 + off) = lo;
            }
        }
        __syncthreads();
    }

    // ---- epilogue: write Y[n][b][o] ----
#pragma unroll
    for (int mm = 0; mm < 4; mm++) {
        int bg = b0 + warp_b * 64 + mm * 16 + (lid >> 2);
#pragma unroll
        for (int nn = 0; nn < 4; nn++) {
            int og = m0 + warp_o * 32 + nn * 8 + (lid & 3) * 2;
            if (og < M) {
                float x0 = acc[mm][nn][0], x1 = acc[mm][nn][1];
                float x2 = acc[mm][nn][2], x3 = acc[mm][nn][3];
                if (relu) {
                    x0 = fmaxf(x0, 0.f); x1 = fmaxf(x1, 0.f);
                    x2 = fmaxf(x2, 0.f); x3 = fmaxf(x3, 0.f);
                }
                float2 v01 = make_float2(x0, x1);
                float2 v23 = make_float2(x2, x3);
                *(float2*)&Y[((size_t)n * 256 + bg) * M + og] = v01;
                *(float2*)&Y[((size_t)n * 256 + bg + 8) * M + og] = v23;
            }
        }
    }
}

// ================= pre/post kernels =================
__global__ void build_a0(const float* __restrict__ Hre, const float* __restrict__ Him) {
    int b = blockIdx.x, t = threadIdx.x;
    const float* hr = Hre + (size_t)b * 2048;
    const float* hi = Him + (size_t)b * 2048;
    float* dst = g_A0 + (size_t)b * 4096;
#pragma unroll
    for (int j = 0; j < 8; j++) {
        int idx = t + j * 256;
        int n = idx >> 5, d = idx & 31;
        dst[n * 64 + d]      = hr[idx];
        dst[n * 64 + 32 + d] = hi[idx];
    }
}

__global__ void bn_partial(const float* __restrict__ Y) {
    int o = blockIdx.x * 256 + threadIdx.x;
    int z = blockIdx.y;
    const float* p = Y + (size_t)z * 256 * CDIM + o;
    float s = 0.f, s2 = 0.f;
#pragma unroll 8
    for (int r = 0; r < 256; r++) {
        float v = p[(size_t)r * CDIM];
        s += v; s2 += v * v;
    }
    g_pS[z * CDIM + o] = s;
    g_pS2[z * CDIM + o] = s2;
}

__global__ void bn_finalize(const float* __restrict__ w, const float* __restrict__ bb) {
    int o = blockIdx.x * 256 + threadIdx.x;
    float s = 0.f, s2 = 0.f;
#pragma unroll
    for (int z = 0; z < 64; z++) { s += g_pS[z * CDIM + o]; s2 += g_pS2[z * CDIM + o]; }
    float mean = s / (float)BL;
    float var  = s2 / (float)BL - mean * mean;
    float sc = w[o] * rsqrtf(var + 1e-5f);
    g_scale[o] = sc;
    g_shift[o] = bb[o] - mean * sc;
}

// elementwise: mean -> g_M[bl][h], softplus(std-channel) -> g_S[bl][h]
__global__ void bn_apply(const float* __restrict__ Y) {
    int nb = blockIdx.x, t = threadIdx.x;
    int n = nb >> 8, b = nb & 255;
    size_t base = (size_t)nb * CDIM;
    size_t mbase = ((size_t)b * 64 + n) * HDIM;
#pragma unroll
    for (int r = 0; r < 2; r++) {
        int d = r * 256 + t;
        float m = g_scale[d] * Y[base + d] + g_shift[d];
        int ds = d + HDIM;
        float x = g_scale[ds] * Y[base + ds] + g_shift[ds];
        float sp = fmaxf(x, 0.f) + log1pf(expf(-fabsf(x))) + 1e-10f;
        g_M[mbase + d] = m;
        g_S[mbase + d] = sp;
    }
}

__global__ void noise_kernel(const float* __restrict__ Nz, int add) {
    int bl = blockIdx.x, t = threadIdx.x;
    float local = 0.f;
#pragma unroll
    for (int h = t; h < HDIM; h += 256) {
        size_t idx = (size_t)bl * HDIM + h;
        float m = g_M[idx], s = g_S[idx];
        float n0 = Nz[idx];
        float n1 = Nz[idx + NS_STRIDE];
        float n2 = Nz[idx + 2 * NS_STRIDE];
        float n3 = Nz[idx + 3 * NS_STRIDE];
        float S1 = (n0 + n1 + n2 + n3) * 0.25f;
        float S2 = (n0 * n0 + n1 * n1 + n2 * n2 + n3 * n3) * 0.25f;
        local += 0.5f * m * m - logf(s) + m * s * S1 + 0.5f * (s * s - 1.0f) * S2;
    }
    __shared__ float sh[256];
    sh[t] = local;
    __syncthreads();
    for (int off = 128; off; off >>= 1) {
        if (t < off) sh[t] += sh[t + off];
        __syncthreads();
    }
    if (t == 0) {
        if (add) g_Ipart[bl] += sh[0];
        else     g_Ipart[bl]  = sh[0];
    }
}

__global__ void pn_kernel() {
    int b = blockIdx.x, t = threadIdx.x;     // 64 threads
    int k = t & 7, j = t >> 3;
    float s = 0.f;
#pragma unroll
    for (int n = j; n < 64; n += 8) {
        float v = g_Y2[((size_t)n * 256 + b) * MOUT + 64 + k];
        s += v * v;
    }
    __shared__ float sh[64];
    sh[t] = s;
    __syncthreads();
    if (t < 8) {
        float tot = 0.f;
#pragma unroll
        for (int j2 = 0; j2 < 8; j2++) tot += sh[j2 * 8 + t];
        g_Pn[b * 8 + t] = sqrtf(tot);
    }
}

__global__ void final_kernel(float* __restrict__ out) {
    int nb = blockIdx.x, t = threadIdx.x;    // 72 threads
    int n = nb >> 8, b = nb & 255;
    __shared__ float v[72];
    __shared__ float mult[8];
    v[t] = g_Y2[(size_t)nb * MOUT + t];
    __syncthreads();
    if (t < 8) {
        float ss = 0.f;
#pragma unroll
        for (int u = 0; u < 4; u++) {
            float a = v[t * 4 + u], c2 = v[32 + t * 4 + u];
            ss += a * a + c2 * c2;
        }
        float f3 = sqrtf(ss);
        float pu = v[64 + t] / g_Pn[b * 8 + t] * 8.0f;   // sqrt(L)=8
        mult[t] = pu / f3;
    }
    __syncthreads();
    if (t < 64) {
        int kk = (t & 31) >> 2;
        size_t obase = ((size_t)b * 64 + n) * 32;
        float r = v[t] * mult[kk];
        if (t < 32) out[OUT_FRE + obase + t] = r;
        else        out[OUT_FIM + obase + (t - 32)] = r;
    }
}

__global__ void write_i(float* __restrict__ out) {
    int b = threadIdx.x;
    float s = 0.f;
#pragma unroll
    for (int n = 0; n < LDIM; n++) s += g_Ipart[b * 64 + n];
    out[OUT_I + b] = s;
}

// ================= launch =================
extern "C" void kernel_launch(void* const* d_in, const int* in_sizes, int n_in,
                              void* d_out, int out_size) {
    const float* Hre = (const float*)d_in[0];
    const float* Him = (const float*)d_in[1];
    const float* P0  = (const float*)d_in[2];
    const float* P1  = (const float*)d_in[3];
    const float* P2  = (const float*)d_in[4];
    const float* w0  = (const float*)d_in[5];
    const float* b0  = (const float*)d_in[6];
    const float* w1  = (const float*)d_in[7];
    const float* b1  = (const float*)d_in[8];
    const float* nz0 = (const float*)d_in[9];
    const float* nz1 = (const float*)d_in[10];
    float* out = (float*)d_out;

    float *A0p, *Yp, *Mp, *Y2p;
    cudaGetSymbolAddress((void**)&A0p, g_A0);
    cudaGetSymbolAddress((void**)&Yp,  g_Y);
    cudaGetSymbolAddress((void**)&Mp,  g_M);
    cudaGetSymbolAddress((void**)&Y2p, g_Y2);

    cudaFuncSetAttribute(gemm_mma, cudaFuncAttributeMaxDynamicSharedMemorySize, GSMEM);

    // layer 0: K=64
    build_a0<<<BDIM, 256>>>(Hre, Him);
    gemm_mma<<<dim3(8, 2, 64), 256, GSMEM>>>(P0, A0p, Yp, DIN, CDIM, 1);
    bn_partial<<<dim3(4, 64), 256>>>(Yp);
    bn_finalize<<<4, 256>>>(w0, b0);
    bn_apply<<<BL, 256>>>(Yp);
    noise_kernel<<<BL, 256>>>(nz0, 0);

    // layer 1: K=512
    gemm_mma<<<dim3(8, 2, 64), 256, GSMEM>>>(P1, Mp, Yp, HDIM, CDIM, 1);
    bn_partial<<<dim3(4, 64), 256>>>(Yp);
    bn_finalize<<<4, 256>>>(w1, b1);
    bn_apply<<<BL, 256>>>(Yp);
    noise_kernel<<<BL, 256>>>(nz1, 1);

    // layer 2: K=512, M=144 (2 o-tiles, second partially valid)
    gemm_mma<<<dim3(2, 2, 64), 256, GSMEM>>>(P2, Mp, Y2p, HDIM, MOUT, 0);

    // epilogue
    pn_kernel<<<BDIM, 64>>>();
    final_kernel<<<BL, 72>>>(out);
    write_i<<<1, BDIM>>>(out);
}

// round 5
// speedup vs baseline: 2.3640x; 1.1147x over previous
#include <cuda_runtime.h>
#include <cuda_bf16.h>
#include <cstdint>

// Problem constants
#define BDIM  256          // B = BATCH*NBR
#define LDIM  64
#define DIN   64           // 2*K*U
#define HDIM  512
#define CDIM  1024         // 2*h
#define MOUT  144
#define BL    16384        // B*L
#define NS_STRIDE ((size_t)BL * HDIM)
#define OUT_FRE  0
#define OUT_FIM  524288
#define OUT_I    1048576

// ---------------- scratch ----------------
__device__ __align__(128) __nv_bfloat16 g_A0h[BDIM * LDIM * DIN];  // 2 MB
__device__ __align__(128) __nv_bfloat16 g_A0l[BDIM * LDIM * DIN];  // 2 MB
__device__ __align__(128) float g_Y [LDIM * BDIM * CDIM];          // 64 MB [n][b][o]
__device__ __align__(128) __nv_bfloat16 g_Mh[BL * HDIM];           // 16 MB [(b*64+n)][h]
__device__ __align__(128) __nv_bfloat16 g_Ml[BL * HDIM];           // 16 MB
__device__ __align__(128) float g_Y2[LDIM * BDIM * MOUT];          //  9 MB [n][b][c]
__device__ float g_pS [256 * CDIM];    // per-slot channel sums
__device__ float g_pS2[256 * CDIM];
__device__ float g_scale[CDIM];
__device__ float g_shift[CDIM];
__device__ float g_Pn[BDIM * 8];
__device__ float g_Ipart[BL];

// ================= helpers =================
__device__ __forceinline__ uint32_t smem_u32(const void* p) {
    uint32_t a;
    asm("{ .reg .u64 t; cvta.to.shared.u64 t, %1; cvt.u32.u64 %0, t; }" : "=r"(a) : "l"(p));
    return a;
}
__device__ __forceinline__ void ldmx4(uint32_t* r, uint32_t addr) {
    asm volatile("ldmatrix.sync.aligned.m8n8.x4.shared.b16 {%0,%1,%2,%3}, [%4];"
        : "=r"(r[0]), "=r"(r[1]), "=r"(r[2]), "=r"(r[3]) : "r"(addr));
}
__device__ __forceinline__ void mma_bf16(float* c, const uint32_t* a,
                                         uint32_t b0, uint32_t b1) {
    asm volatile("mma.sync.aligned.m16n8k16.row.col.f32.bf16.bf16.f32 "
        "{%0,%1,%2,%3}, {%4,%5,%6,%7}, {%8,%9}, {%0,%1,%2,%3};"
        : "+f"(c[0]), "+f"(c[1]), "+f"(c[2]), "+f"(c[3])
        : "r"(a[0]), "r"(a[1]), "r"(a[2]), "r"(a[3]), "r"(b0), "r"(b1));
}
__device__ __forceinline__ uint32_t bf2u(__nv_bfloat162 h) {
    return *reinterpret_cast<uint32_t*>(&h);
}
__device__ __forceinline__ void cvt_hilo(float4 v, uint2& hi, uint2& lo) {
    __nv_bfloat162 h01 = __floats2bfloat162_rn(v.x, v.y);
    __nv_bfloat162 h23 = __floats2bfloat162_rn(v.z, v.w);
    float2 f01 = __bfloat1622float2(h01);
    float2 f23 = __bfloat1622float2(h23);
    __nv_bfloat162 l01 = __floats2bfloat162_rn(v.x - f01.x, v.y - f01.y);
    __nv_bfloat162 l23 = __floats2bfloat162_rn(v.z - f23.x, v.w - f23.y);
    hi.x = bf2u(h01); hi.y = bf2u(h23);
    lo.x = bf2u(l01); lo.y = bf2u(l23);
}

// ================= tensor-core batched GEMM (mma.sync bf16 3-term) =================
// Y[n][b][o] = sum_d P[n][o][d] * Act[(b*64+n)][d]; Act given as bf16 hi/lo arrays.
// CTA tile: 128 b x 128 o x 64 k; 8 warps (2 b x 4 o), warp tile 64x32.
// smem buffer: AH 16K | AL 16K | PH 16K | PL 16K ; double buffered.
#define GBUF 65536
#define GSMEM (2 * GBUF)

__global__ __launch_bounds__(256) void gemm_mma(
    const float* __restrict__ Pw,
    const __nv_bfloat16* __restrict__ Ah, const __nv_bfloat16* __restrict__ Al,
    float* __restrict__ Y, int K, int M, int relu, int stats)
{
    extern __shared__ char sm[];
    const int tid = threadIdx.x, wid = tid >> 5, lid = tid & 31;
    const int m0 = blockIdx.x * 128, b0 = blockIdx.y * 128, n = blockIdx.z;
    const int nchunk = K >> 6;
    uint32_t sb = smem_u32(sm);

    // global-load indexing
    const int r0 = tid >> 4, c4 = tid & 15;
    // P: 8B granule swizzle (granule idx = c4>>1, halves by c4&1)
    const int cswP = (((c4 >> 1) ^ (r0 & 7)) << 4) + (c4 & 1) * 8;
    // A: 16B granule; threads c4<8 load hi, c4>=8 load lo
    const int ac = c4 & 7;
    const int aregion = (c4 < 8) ? 0 : 16384;
    const int cswA = ((ac ^ (r0 & 7)) << 4);
    const __nv_bfloat16* Asrc = (c4 < 8) ? Ah : Al;

    // ldmatrix lane geometry
    const int lr  = (lid & 7) + ((lid >> 3) & 1) * 8;
    const int kch = lid >> 4;
    const int warp_b = wid >> 2, warp_o = wid & 3;
    int rowA128[4], r7A[4], rowB128[2], r7B[2];
#pragma unroll
    for (int mm = 0; mm < 4; mm++) {
        int r = warp_b * 64 + mm * 16 + lr;
        rowA128[mm] = r * 128; r7A[mm] = r & 7;
    }
#pragma unroll
    for (int g = 0; g < 2; g++) {
        int r = warp_o * 32 + g * 16 + lr;
        rowB128[g] = r * 128; r7B[g] = r & 7;
    }

    float acc[4][4][4];
#pragma unroll
    for (int i = 0; i < 4; i++)
#pragma unroll
        for (int j = 0; j < 4; j++)
#pragma unroll
            for (int q = 0; q < 4; q++) acc[i][j][q] = 0.f;

    uint4 stA[8];
    float4 stP[8];

    // ---- prologue: load chunk 0 ----
#pragma unroll
    for (int j = 0; j < 8; j++) {
        int row = j * 16 + r0;
        stA[j] = *(const uint4*)&Asrc[((size_t)(b0 + row) * 64 + n) * K + ac * 8];
        if (m0 + row < M)
            stP[j] = *(const float4*)&Pw[((size_t)n * M + m0 + row) * K + c4 * 4];
        else stP[j] = make_float4(0.f, 0.f, 0.f, 0.f);
    }
    {
        char* buf = sm;
#pragma unroll
        for (int j = 0; j < 8; j++) {
            int row = j * 16 + r0;
            *(uint4*)(buf + aregion + row * 128 + cswA) = stA[j];
            uint2 hi, lo;
            cvt_hilo(stP[j], hi, lo);
            *(uint2*)(buf + 32768 + row * 128 + cswP) = hi;
            *(uint2*)(buf + 49152 + row * 128 + cswP) = lo;
        }
    }
    __syncthreads();

    for (int c = 0; c < nchunk; c++) {
        if (c + 1 < nchunk) {
            int k0 = (c + 1) << 6;
#pragma unroll
            for (int j = 0; j < 8; j++) {
                int row = j * 16 + r0;
                stA[j] = *(const uint4*)&Asrc[((size_t)(b0 + row) * 64 + n) * K + k0 + ac * 8];
                if (m0 + row < M)
                    stP[j] = *(const float4*)&Pw[((size_t)n * M + m0 + row) * K + k0 + c4 * 4];
                else stP[j] = make_float4(0.f, 0.f, 0.f, 0.f);
            }
        }

        // ---- compute on buffer c&1 ----
        uint32_t ub = sb + (c & 1) * GBUF;
#pragma unroll
        for (int kk = 0; kk < 4; kk++) {
            uint32_t ah[4][4], al[4][4], bh[2][4], bl2[2][4];
            int ksel = kk * 2 + kch;
#pragma unroll
            for (int mm = 0; mm < 4; mm++)
                ldmx4(ah[mm], ub + rowA128[mm] + ((ksel ^ r7A[mm]) << 4));
#pragma unroll
            for (int mm = 0; mm < 4; mm++)
                ldmx4(al[mm], ub + 16384 + rowA128[mm] + ((ksel ^ r7A[mm]) << 4));
#pragma unroll
            for (int g = 0; g < 2; g++)
                ldmx4(bh[g], ub + 32768 + rowB128[g] + ((ksel ^ r7B[g]) << 4));
#pragma unroll
            for (int g = 0; g < 2; g++)
                ldmx4(bl2[g], ub + 49152 + rowB128[g] + ((ksel ^ r7B[g]) << 4));
#pragma unroll
            for (int mm = 0; mm < 4; mm++)
#pragma unroll
                for (int nn = 0; nn < 4; nn++) {
                    int g = nn >> 1, s = nn & 1;
                    mma_bf16(acc[mm][nn], ah[mm], bh[g][s],  bh[g][s + 2]);
                    mma_bf16(acc[mm][nn], ah[mm], bl2[g][s], bl2[g][s + 2]);
                    mma_bf16(acc[mm][nn], al[mm], bh[g][s],  bh[g][s + 2]);
                }
        }

        if (c + 1 < nchunk) {
            char* buf = sm + ((c + 1) & 1) * GBUF;
#pragma unroll
            for (int j = 0; j < 8; j++) {
                int row = j * 16 + r0;
                *(uint4*)(buf + aregion + row * 128 + cswA) = stA[j];
                uint2 hi, lo;
                cvt_hilo(stP[j], hi, lo);
                *(uint2*)(buf + 32768 + row * 128 + cswP) = hi;
                *(uint2*)(buf + 49152 + row * 128 + cswP) = lo;
            }
        }
        __syncthreads();
    }

    // ---- epilogue ----
    if (relu) {
#pragma unroll
        for (int i = 0; i < 4; i++)
#pragma unroll
            for (int j = 0; j < 4; j++)
#pragma unroll
                for (int q = 0; q < 4; q++) acc[i][j][q] = fmaxf(acc[i][j][q], 0.f);
    }

#pragma unroll
    for (int mm = 0; mm < 4; mm++) {
        int bg = b0 + warp_b * 64 + mm * 16 + (lid >> 2);
#pragma unroll
        for (int nn = 0; nn < 4; nn++) {
            int og = m0 + warp_o * 32 + nn * 8 + (lid & 3) * 2;
            if (og < M) {
                float2 v01 = make_float2(acc[mm][nn][0], acc[mm][nn][1]);
                float2 v23 = make_float2(acc[mm][nn][2], acc[mm][nn][3]);
                *(float2*)&Y[((size_t)n * 256 + bg) * M + og] = v01;
                *(float2*)&Y[((size_t)n * 256 + bg + 8) * M + og] = v23;
            }
        }
    }

    // fused BN partial stats (deterministic per-slot, no atomics)
    if (stats) {
        float s1[8], s2v[8];
#pragma unroll
        for (int k = 0; k < 8; k++) { s1[k] = 0.f; s2v[k] = 0.f; }
#pragma unroll
        for (int nn = 0; nn < 4; nn++)
#pragma unroll
            for (int q = 0; q < 2; q++) {
                int k = nn * 2 + q;
#pragma unroll
                for (int mm = 0; mm < 4; mm++) {
                    float v0 = acc[mm][nn][q], v1 = acc[mm][nn][q + 2];
                    s1[k] += v0 + v1;
                    s2v[k] += v0 * v0 + v1 * v1;
                }
            }
#pragma unroll
        for (int k = 0; k < 8; k++)
#pragma unroll
            for (int msk = 4; msk <= 16; msk <<= 1) {
                s1[k]  += __shfl_xor_sync(0xFFFFFFFFu, s1[k],  msk);
                s2v[k] += __shfl_xor_sync(0xFFFFFFFFu, s2v[k], msk);
            }
        if ((lid >> 2) == 0) {
            int slot = (blockIdx.y * 64 + blockIdx.z) * 2 + warp_b;
#pragma unroll
            for (int nn = 0; nn < 4; nn++)
#pragma unroll
                for (int q = 0; q < 2; q++) {
                    int ch = m0 + warp_o * 32 + nn * 8 + (lid & 3) * 2 + q;
                    g_pS [slot * CDIM + ch] = s1[nn * 2 + q];
                    g_pS2[slot * CDIM + ch] = s2v[nn * 2 + q];
                }
        }
    }
}

// ================= pre/post kernels =================
__global__ void build_a0(const float* __restrict__ Hre, const float* __restrict__ Him) {
    int b = blockIdx.x, t = threadIdx.x;
    const float* hr = Hre + (size_t)b * 2048;
    const float* hi = Him + (size_t)b * 2048;
    size_t dbase = (size_t)b * 4096;
#pragma unroll
    for (int j = 0; j < 8; j++) {
        int idx = t + j * 256;
        int n = idx >> 5, d = idx & 31;
        float v0 = hr[idx], v1 = hi[idx];
        __nv_bfloat16 h0 = __float2bfloat16(v0);
        __nv_bfloat16 h1 = __float2bfloat16(v1);
        g_A0h[dbase + n * 64 + d]      = h0;
        g_A0h[dbase + n * 64 + 32 + d] = h1;
        g_A0l[dbase + n * 64 + d]      = __float2bfloat16(v0 - __bfloat162float(h0));
        g_A0l[dbase + n * 64 + 32 + d] = __float2bfloat16(v1 - __bfloat162float(h1));
    }
}

__global__ void bn_finalize(const float* __restrict__ w, const float* __restrict__ bb) {
    int o = blockIdx.x * 128 + threadIdx.x;
    float s = 0.f, s2 = 0.f;
#pragma unroll 8
    for (int sl = 0; sl < 256; sl++) {
        s  += g_pS [sl * CDIM + o];
        s2 += g_pS2[sl * CDIM + o];
    }
    float mean = s / (float)BL;
    float var  = s2 / (float)BL - mean * mean;
    float sc = w[o] * rsqrtf(var + 1e-5f);
    g_scale[o] = sc;
    g_shift[o] = bb[o] - mean * sc;
}

// fused BN-apply + softplus + closed-form noise MI; writes next-layer act (bf16 hi/lo)
__global__ void bn_noise(const float* __restrict__ Y, const float* __restrict__ Nz, int add) {
    int nb = blockIdx.x, t = threadIdx.x;   // 256 threads
    int n = nb >> 8, b = nb & 255;
    size_t ybase = (size_t)nb * CDIM;
    size_t bl = (size_t)b * 64 + n;
    size_t mbase = bl * HDIM;
    float local = 0.f;
#pragma unroll
    for (int r = 0; r < 2; r++) {
        int d = r * 256 + t;
        float m = g_scale[d] * Y[ybase + d] + g_shift[d];
        __nv_bfloat16 mh = __float2bfloat16(m);
        g_Mh[mbase + d] = mh;
        g_Ml[mbase + d] = __float2bfloat16(m - __bfloat162float(mh));
        int ds = d + HDIM;
        float x = g_scale[ds] * Y[ybase + ds] + g_shift[ds];
        float s = fmaxf(x, 0.f) + log1pf(expf(-fabsf(x))) + 1e-10f;
        float n0 = Nz[mbase + d];
        float n1 = Nz[mbase + d + NS_STRIDE];
        float n2 = Nz[mbase + d + 2 * NS_STRIDE];
        float n3 = Nz[mbase + d + 3 * NS_STRIDE];
        float S1 = (n0 + n1 + n2 + n3) * 0.25f;
        float S2 = (n0 * n0 + n1 * n1 + n2 * n2 + n3 * n3) * 0.25f;
        local += 0.5f * m * m - logf(s) + m * s * S1 + 0.5f * (s * s - 1.0f) * S2;
    }
    __shared__ float sh[256];
    sh[t] = local;
    __syncthreads();
    for (int off = 128; off; off >>= 1) {
        if (t < off) sh[t] += sh[t + off];
        __syncthreads();
    }
    if (t == 0) {
        if (add) g_Ipart[bl] += sh[0];
        else     g_Ipart[bl]  = sh[0];
    }
}

__global__ void pn_kernel() {
    int b = blockIdx.x, t = threadIdx.x;     // 64 threads
    int k = t & 7, j = t >> 3;
    float s = 0.f;
#pragma unroll
    for (int n = j; n < 64; n += 8) {
        float v = g_Y2[((size_t)n * 256 + b) * MOUT + 64 + k];
        s += v * v;
    }
    __shared__ float sh[64];
    sh[t] = s;
    __syncthreads();
    if (t < 8) {
        float tot = 0.f;
#pragma unroll
        for (int j2 = 0; j2 < 8; j2++) tot += sh[j2 * 8 + t];
        g_Pn[b * 8 + t] = sqrtf(tot);
    }
}

__global__ void final_kernel(float* __restrict__ out) {
    int nb = blockIdx.x, t = threadIdx.x;    // 72 threads
    int n = nb >> 8, b = nb & 255;
    __shared__ float v[72];
    __shared__ float mult[8];
    v[t] = g_Y2[(size_t)nb * MOUT + t];
    __syncthreads();
    if (t < 8) {
        float ss = 0.f;
#pragma unroll
        for (int u = 0; u < 4; u++) {
            float a = v[t * 4 + u], c2 = v[32 + t * 4 + u];
            ss += a * a + c2 * c2;
        }
        float f3 = sqrtf(ss);
        float pu = v[64 + t] / g_Pn[b * 8 + t] * 8.0f;   // sqrt(L)=8
        mult[t] = pu / f3;
    }
    __syncthreads();
    if (t < 64) {
        int kk = (t & 31) >> 2;
        size_t obase = ((size_t)b * 64 + n) * 32;
        float r = v[t] * mult[kk];
        if (t < 32) out[OUT_FRE + obase + t] = r;
        else        out[OUT_FIM + obase + (t - 32)] = r;
    }
}

__global__ void write_i(float* __restrict__ out) {
    int b = threadIdx.x;
    float s = 0.f;
#pragma unroll
    for (int n = 0; n < LDIM; n++) s += g_Ipart[b * 64 + n];
    out[OUT_I + b] = s;
}

// ================= launch =================
extern "C" void kernel_launch(void* const* d_in, const int* in_sizes, int n_in,
                              void* d_out, int out_size) {
    const float* Hre = (const float*)d_in[0];
    const float* Him = (const float*)d_in[1];
    const float* P0  = (const float*)d_in[2];
    const float* P1  = (const float*)d_in[3];
    const float* P2  = (const float*)d_in[4];
    const float* w0  = (const float*)d_in[5];
    const float* b0  = (const float*)d_in[6];
    const float* w1  = (const float*)d_in[7];
    const float* b1  = (const float*)d_in[8];
    const float* nz0 = (const float*)d_in[9];
    const float* nz1 = (const float*)d_in[10];
    float* out = (float*)d_out;

    float *Yp, *Y2p;
    __nv_bfloat16 *A0h, *A0l, *Mh, *Ml;
    cudaGetSymbolAddress((void**)&A0h, g_A0h);
    cudaGetSymbolAddress((void**)&A0l, g_A0l);
    cudaGetSymbolAddress((void**)&Yp,  g_Y);
    cudaGetSymbolAddress((void**)&Mh,  g_Mh);
    cudaGetSymbolAddress((void**)&Ml,  g_Ml);
    cudaGetSymbolAddress((void**)&Y2p, g_Y2);

    cudaFuncSetAttribute(gemm_mma, cudaFuncAttributeMaxDynamicSharedMemorySize, GSMEM);

    // layer 0: K=64
    build_a0<<<BDIM, 256>>>(Hre, Him);
    gemm_mma<<<dim3(8, 2, 64), 256, GSMEM>>>(P0, A0h, A0l, Yp, DIN, CDIM, 1, 1);
    bn_finalize<<<8, 128>>>(w0, b0);
    bn_noise<<<BL, 256>>>(Yp, nz0, 0);

    // layer 1: K=512
    gemm_mma<<<dim3(8, 2, 64), 256, GSMEM>>>(P1, Mh, Ml, Yp, HDIM, CDIM, 1, 1);
    bn_finalize<<<8, 128>>>(w1, b1);
    bn_noise<<<BL, 256>>>(Yp, nz1, 1);

    // layer 2: K=512, M=144 (2 o-tiles, second partially valid)
    gemm_mma<<<dim3(2, 2, 64), 256, GSMEM>>>(P2, Mh, Ml, Y2p, HDIM, MOUT, 0, 0);

    // epilogue
    pn_kernel<<<BDIM, 64>>>();
    final_kernel<<<BL, 72>>>(out);
    write_i<<<1, BDIM>>>(out);
}

// round 6
// speedup vs baseline: 3.1899x; 1.3494x over previous
#include <cuda_runtime.h>
#include <cuda_fp16.h>
#include <cstdint>

// Problem constants
#define BDIM  256          // B = BATCH*NBR
#define LDIM  64
#define DIN   64           // 2*K*U
#define HDIM  512
#define CDIM  1024         // 2*h
#define MOUT  144
#define BL    16384        // B*L
#define NS_STRIDE ((size_t)BL * HDIM)
#define OUT_FRE  0
#define OUT_FIM  524288
#define OUT_I    1048576

// ---------------- scratch ----------------
__device__ __align__(128) __half g_A0h[BDIM * LDIM * DIN];   // 2 MB
__device__ __align__(128) __half g_A0l[BDIM * LDIM * DIN];   // 2 MB
__device__ __align__(128) float g_Y [LDIM * BDIM * CDIM];    // 64 MB [n][b][o]
__device__ __align__(128) __half g_Mh[BL * HDIM];            // 16 MB [(b*64+n)][h]
__device__ __align__(128) __half g_Ml[BL * HDIM];            // 16 MB
__device__ __align__(128) float g_Y2[LDIM * BDIM * MOUT];    //  9 MB [n][b][c]
__device__ float g_pS [256 * CDIM];
__device__ float g_pS2[256 * CDIM];
__device__ float g_scale[CDIM];
__device__ float g_shift[CDIM];
__device__ float g_Ipart[BL];

// ================= helpers =================
__device__ __forceinline__ uint32_t smem_u32(const void* p) {
    uint32_t a;
    asm("{ .reg .u64 t; cvta.to.shared.u64 t, %1; cvt.u32.u64 %0, t; }" : "=r"(a) : "l"(p));
    return a;
}
__device__ __forceinline__ void ldmx4(uint32_t* r, uint32_t addr) {
    asm volatile("ldmatrix.sync.aligned.m8n8.x4.shared.b16 {%0,%1,%2,%3}, [%4];"
        : "=r"(r[0]), "=r"(r[1]), "=r"(r[2]), "=r"(r[3]) : "r"(addr));
}
__device__ __forceinline__ void mma_f16(float* c, const uint32_t* a,
                                        uint32_t b0, uint32_t b1) {
    asm volatile("mma.sync.aligned.m16n8k16.row.col.f32.f16.f16.f32 "
        "{%0,%1,%2,%3}, {%4,%5,%6,%7}, {%8,%9}, {%0,%1,%2,%3};"
        : "+f"(c[0]), "+f"(c[1]), "+f"(c[2]), "+f"(c[3])
        : "r"(a[0]), "r"(a[1]), "r"(a[2]), "r"(a[3]), "r"(b0), "r"(b1));
}
#define CP_ASYNC16(dst, src) \
    asm volatile("cp.async.ca.shared.global [%0], [%1], 16;" :: "r"(dst), "l"(src))
#define CP_COMMIT() asm volatile("cp.async.commit_group;")
#define CP_WAIT0()  asm volatile("cp.async.wait_group 0;")

__device__ __forceinline__ uint2 cvt4h(float4 v) {
    __half2 a = __floats2half2_rn(v.x, v.y);
    __half2 b = __floats2half2_rn(v.z, v.w);
    uint2 r;
    r.x = *reinterpret_cast<uint32_t*>(&a);
    r.y = *reinterpret_cast<uint32_t*>(&b);
    return r;
}

// ================= tensor-core batched GEMM (fp16 2-term: Ph*Ahi + Ph*Alo) ======
// Y[n][b][o] = sum_d P[n][o][d] * Act[(b*64+n)][d]
// CTA tile 128b x 128o x 64k; 8 warps (2b x 4o), warp tile 64x32.
// smem buffer: AH 16K | AL 16K | PH 16K ; double buffered (96 KB).
#define GBUF 49152
#define GSMEM (2 * GBUF)

__global__ __launch_bounds__(256) void gemm_mma(
    const float* __restrict__ Pw,
    const __half* __restrict__ Ah, const __half* __restrict__ Al,
    float* __restrict__ Y, int K, int M, int relu, int stats)
{
    extern __shared__ char sm[];
    const int tid = threadIdx.x, wid = tid >> 5, lid = tid & 31;
    const int m0 = blockIdx.x * 128, b0 = blockIdx.y * 128, n = blockIdx.z;
    const int nchunk = K >> 6;
    uint32_t sb = smem_u32(sm);

    // global-load indexing
    const int r0 = tid >> 4, c4 = tid & 15;
    const int cswP = (((c4 >> 1) ^ (r0 & 7)) << 4) + (c4 & 1) * 8;
    const int ac = c4 & 7;
    const int aregion = (c4 < 8) ? 0 : 16384;
    const int cswA = ((ac ^ (r0 & 7)) << 4);
    const __half* Asrc = (c4 < 8) ? Ah : Al;

    // ldmatrix lane geometry
    const int lr  = (lid & 7) + ((lid >> 3) & 1) * 8;
    const int kch = lid >> 4;
    const int warp_b = wid >> 2, warp_o = wid & 3;
    int rowA128[4], r7A[4], rowB128[2], r7B[2];
#pragma unroll
    for (int mm = 0; mm < 4; mm++) {
        int r = warp_b * 64 + mm * 16 + lr;
        rowA128[mm] = r * 128; r7A[mm] = r & 7;
    }
#pragma unroll
    for (int g = 0; g < 2; g++) {
        int r = warp_o * 32 + g * 16 + lr;
        rowB128[g] = r * 128; r7B[g] = r & 7;
    }

    float acc[4][4][4];
#pragma unroll
    for (int i = 0; i < 4; i++)
#pragma unroll
        for (int j = 0; j < 4; j++)
#pragma unroll
            for (int q = 0; q < 4; q++) acc[i][j][q] = 0.f;

    float4 stP[8];

    // ---- prologue: chunk 0 ----
#pragma unroll
    for (int j = 0; j < 8; j++) {
        int row = j * 16 + r0;
        const void* src = &Asrc[((size_t)(b0 + row) * 64 + n) * K + ac * 8];
        CP_ASYNC16(sb + aregion + row * 128 + cswA, src);
    }
    CP_COMMIT();
#pragma unroll
    for (int j = 0; j < 8; j++) {
        int row = j * 16 + r0;
        if (m0 + row < M)
            stP[j] = *(const float4*)&Pw[((size_t)n * M + m0 + row) * K + c4 * 4];
        else stP[j] = make_float4(0.f, 0.f, 0.f, 0.f);
    }
#pragma unroll
    for (int j = 0; j < 8; j++) {
        int row = j * 16 + r0;
        *(uint2*)(sm + 32768 + row * 128 + cswP) = cvt4h(stP[j]);
    }
    CP_WAIT0();
    __syncthreads();

    for (int c = 0; c < nchunk; c++) {
        if (c + 1 < nchunk) {
            int k0 = (c + 1) << 6;
            uint32_t bdst = sb + ((c + 1) & 1) * GBUF;
#pragma unroll
            for (int j = 0; j < 8; j++) {
                int row = j * 16 + r0;
                const void* src = &Asrc[((size_t)(b0 + row) * 64 + n) * K + k0 + ac * 8];
                CP_ASYNC16(bdst + aregion + row * 128 + cswA, src);
            }
            CP_COMMIT();
#pragma unroll
            for (int j = 0; j < 8; j++) {
                int row = j * 16 + r0;
                if (m0 + row < M)
                    stP[j] = *(const float4*)&Pw[((size_t)n * M + m0 + row) * K + k0 + c4 * 4];
                else stP[j] = make_float4(0.f, 0.f, 0.f, 0.f);
            }
        }

        // ---- compute on buffer c&1 ----
        uint32_t ub = sb + (c & 1) * GBUF;
#pragma unroll
        for (int kk = 0; kk < 4; kk++) {
            uint32_t ah[4][4], al[4][4], bh[2][4];
            int ksel = kk * 2 + kch;
#pragma unroll
            for (int mm = 0; mm < 4; mm++)
                ldmx4(ah[mm], ub + rowA128[mm] + ((ksel ^ r7A[mm]) << 4));
#pragma unroll
            for (int mm = 0; mm < 4; mm++)
                ldmx4(al[mm], ub + 16384 + rowA128[mm] + ((ksel ^ r7A[mm]) << 4));
#pragma unroll
            for (int g = 0; g < 2; g++)
                ldmx4(bh[g], ub + 32768 + rowB128[g] + ((ksel ^ r7B[g]) << 4));
#pragma unroll
            for (int mm = 0; mm < 4; mm++)
#pragma unroll
                for (int nn = 0; nn < 4; nn++) {
                    int g = nn >> 1, s = nn & 1;
                    mma_f16(acc[mm][nn], ah[mm], bh[g][s], bh[g][s + 2]);
                    mma_f16(acc[mm][nn], al[mm], bh[g][s], bh[g][s + 2]);
                }
        }

        if (c + 1 < nchunk) {
            char* buf = sm + ((c + 1) & 1) * GBUF;
#pragma unroll
            for (int j = 0; j < 8; j++) {
                int row = j * 16 + r0;
                *(uint2*)(buf + 32768 + row * 128 + cswP) = cvt4h(stP[j]);
            }
            CP_WAIT0();
        }
        __syncthreads();
    }

    // ---- epilogue ----
    if (relu) {
#pragma unroll
        for (int i = 0; i < 4; i++)
#pragma unroll
            for (int j = 0; j < 4; j++)
#pragma unroll
                for (int q = 0; q < 4; q++) acc[i][j][q] = fmaxf(acc[i][j][q], 0.f);
    }

#pragma unroll
    for (int mm = 0; mm < 4; mm++) {
        int bg = b0 + warp_b * 64 + mm * 16 + (lid >> 2);
#pragma unroll
        for (int nn = 0; nn < 4; nn++) {
            int og = m0 + warp_o * 32 + nn * 8 + (lid & 3) * 2;
            if (og < M) {
                float2 v01 = make_float2(acc[mm][nn][0], acc[mm][nn][1]);
                float2 v23 = make_float2(acc[mm][nn][2], acc[mm][nn][3]);
                *(float2*)&Y[((size_t)n * 256 + bg) * M + og] = v01;
                *(float2*)&Y[((size_t)n * 256 + bg + 8) * M + og] = v23;
            }
        }
    }

    // fused BN partial stats (deterministic per-slot, no atomics)
    if (stats) {
        float s1[8], s2v[8];
#pragma unroll
        for (int k = 0; k < 8; k++) { s1[k] = 0.f; s2v[k] = 0.f; }
#pragma unroll
        for (int nn = 0; nn < 4; nn++)
#pragma unroll
            for (int q = 0; q < 2; q++) {
                int k = nn * 2 + q;
#pragma unroll
                for (int mm = 0; mm < 4; mm++) {
                    float v0 = acc[mm][nn][q], v1 = acc[mm][nn][q + 2];
                    s1[k] += v0 + v1;
                    s2v[k] += v0 * v0 + v1 * v1;
                }
            }
#pragma unroll
        for (int k = 0; k < 8; k++)
#pragma unroll
            for (int msk = 4; msk <= 16; msk <<= 1) {
                s1[k]  += __shfl_xor_sync(0xFFFFFFFFu, s1[k],  msk);
                s2v[k] += __shfl_xor_sync(0xFFFFFFFFu, s2v[k], msk);
            }
        if ((lid >> 2) == 0) {
            int slot = (blockIdx.y * 64 + blockIdx.z) * 2 + warp_b;
#pragma unroll
            for (int nn = 0; nn < 4; nn++)
#pragma unroll
                for (int q = 0; q < 2; q++) {
                    int ch = m0 + warp_o * 32 + nn * 8 + (lid & 3) * 2 + q;
                    g_pS [slot * CDIM + ch] = s1[nn * 2 + q];
                    g_pS2[slot * CDIM + ch] = s2v[nn * 2 + q];
                }
        }
    }
}

// ================= pre/post kernels =================
__global__ void build_a0(const float* __restrict__ Hre, const float* __restrict__ Him) {
    int b = blockIdx.x, t = threadIdx.x;
    const float* hr = Hre + (size_t)b * 2048;
    const float* hi = Him + (size_t)b * 2048;
    size_t dbase = (size_t)b * 4096;
#pragma unroll
    for (int j = 0; j < 8; j++) {
        int idx = t + j * 256;
        int n = idx >> 5, d = idx & 31;
        float v0 = hr[idx], v1 = hi[idx];
        __half h0 = __float2half_rn(v0);
        __half h1 = __float2half_rn(v1);
        g_A0h[dbase + n * 64 + d]      = h0;
        g_A0h[dbase + n * 64 + 32 + d] = h1;
        g_A0l[dbase + n * 64 + d]      = __float2half_rn(v0 - __half2float(h0));
        g_A0l[dbase + n * 64 + 32 + d] = __float2half_rn(v1 - __half2float(h1));
    }
}

__global__ void bn_finalize(const float* __restrict__ w, const float* __restrict__ bb) {
    int o = blockIdx.x * 128 + threadIdx.x;
    float s = 0.f, s2 = 0.f;
#pragma unroll 8
    for (int sl = 0; sl < 256; sl++) {
        s  += g_pS [sl * CDIM + o];
        s2 += g_pS2[sl * CDIM + o];
    }
    float mean = s / (float)BL;
    float var  = s2 / (float)BL - mean * mean;
    float sc = w[o] * rsqrtf(var + 1e-5f);
    g_scale[o] = sc;
    g_shift[o] = bb[o] - mean * sc;
}

// fused BN-apply + softplus + closed-form noise MI; vectorized float4, 128 thr/blk
__global__ void bn_noise(const float* __restrict__ Y, const float* __restrict__ Nz, int add) {
    int nb = blockIdx.x, t = threadIdx.x;
    int n = nb >> 8, b = nb & 255;
    size_t ybase = (size_t)nb * CDIM;
    size_t bl = (size_t)b * 64 + n;
    size_t mbase = bl * HDIM;
    int d = t * 4;

    float4 ym = *(const float4*)&Y[ybase + d];
    float4 ys = *(const float4*)&Y[ybase + HDIM + d];
    float4 scm = *(const float4*)&g_scale[d];
    float4 shm = *(const float4*)&g_shift[d];
    float4 scs = *(const float4*)&g_scale[HDIM + d];
    float4 shs = *(const float4*)&g_shift[HDIM + d];
    float4 n0 = *(const float4*)&Nz[mbase + d];
    float4 n1 = *(const float4*)&Nz[mbase + d + NS_STRIDE];
    float4 n2 = *(const float4*)&Nz[mbase + d + 2 * NS_STRIDE];
    float4 n3 = *(const float4*)&Nz[mbase + d + 3 * NS_STRIDE];

    float m[4] = { scm.x * ym.x + shm.x, scm.y * ym.y + shm.y,
                   scm.z * ym.z + shm.z, scm.w * ym.w + shm.w };
    float x[4] = { scs.x * ys.x + shs.x, scs.y * ys.y + shs.y,
                   scs.z * ys.z + shs.z, scs.w * ys.w + shs.w };
    float nn0[4] = { n0.x, n0.y, n0.z, n0.w };
    float nn1[4] = { n1.x, n1.y, n1.z, n1.w };
    float nn2[4] = { n2.x, n2.y, n2.z, n2.w };
    float nn3[4] = { n3.x, n3.y, n3.z, n3.w };

    float local = 0.f;
    float lo[4];
#pragma unroll
    for (int i = 0; i < 4; i++) {
        float s = fmaxf(x[i], 0.f) + log1pf(__expf(-fabsf(x[i]))) + 1e-10f;
        float S1 = (nn0[i] + nn1[i] + nn2[i] + nn3[i]) * 0.25f;
        float S2 = (nn0[i] * nn0[i] + nn1[i] * nn1[i] +
                    nn2[i] * nn2[i] + nn3[i] * nn3[i]) * 0.25f;
        local += 0.5f * m[i] * m[i] - __logf(s) + m[i] * s * S1
               + 0.5f * (s * s - 1.0f) * S2;
        __half mh = __float2half_rn(m[i]);
        lo[i] = m[i] - __half2float(mh);
        m[i] = __half2float(mh);
    }
    __half2 mh01 = __floats2half2_rn(m[0], m[1]);
    __half2 mh23 = __floats2half2_rn(m[2], m[3]);
    __half2 ml01 = __floats2half2_rn(lo[0], lo[1]);
    __half2 ml23 = __floats2half2_rn(lo[2], lo[3]);
    uint2 hv, lv;
    hv.x = *reinterpret_cast<uint32_t*>(&mh01);
    hv.y = *reinterpret_cast<uint32_t*>(&mh23);
    lv.x = *reinterpret_cast<uint32_t*>(&ml01);
    lv.y = *reinterpret_cast<uint32_t*>(&ml23);
    *(uint2*)&g_Mh[mbase + d] = hv;
    *(uint2*)&g_Ml[mbase + d] = lv;

    __shared__ float sh[128];
    sh[t] = local;
    __syncthreads();
    for (int off = 64; off; off >>= 1) {
        if (t < off) sh[t] += sh[t + off];
        __syncthreads();
    }
    if (t == 0) {
        if (add) g_Ipart[bl] += sh[0];
        else     g_Ipart[bl]  = sh[0];
    }
}

// merged pn + final + I-sum: one block per b (256 blocks, 128 threads)
__global__ void epilogue_kernel(float* __restrict__ out) {
    int b = blockIdx.x, t = threadIdx.x;
    __shared__ float v[64][72];
    __shared__ float pk[64];
    __shared__ float Pn[8];
    __shared__ float mult[64][8];

    for (int idx = t; idx < 64 * 72; idx += 128) {
        int n = idx / 72, c = idx % 72;
        v[n][c] = g_Y2[((size_t)(n * 256 + b)) * MOUT + c];
    }
    __syncthreads();
    if (t < 64) {
        int k = t & 7, j = t >> 3;
        float s = 0.f;
#pragma unroll
        for (int n = j; n < 64; n += 8) { float x = v[n][64 + k]; s += x * x; }
        pk[t] = s;
    }
    __syncthreads();
    if (t < 8) {
        float tot = 0.f;
#pragma unroll
        for (int j = 0; j < 8; j++) tot += pk[j * 8 + t];
        Pn[t] = sqrtf(tot);
    }
    __syncthreads();
    for (int idx = t; idx < 512; idx += 128) {
        int n = idx >> 3, k = idx & 7;
        float ss = 0.f;
#pragma unroll
        for (int u = 0; u < 4; u++) {
            float a = v[n][k * 4 + u], c2 = v[n][32 + k * 4 + u];
            ss += a * a + c2 * c2;
        }
        mult[n][k] = v[n][64 + k] / Pn[k] * 8.0f / sqrtf(ss);  // sqrt(L)=8
    }
    __syncthreads();
    for (int idx = t; idx < 64 * 32; idx += 128) {
        int n = idx >> 5, c = idx & 31;
        size_t obase = ((size_t)b * 64 + n) * 32;
        float mlt = mult[n][c >> 2];
        out[OUT_FRE + obase + c] = v[n][c] * mlt;
        out[OUT_FIM + obase + c] = v[n][32 + c] * mlt;
    }
    if (t < 64) pk[t] = g_Ipart[(size_t)b * 64 + t];
    __syncthreads();
    if (t == 0) {
        float s = 0.f;
#pragma unroll
        for (int n = 0; n < 64; n++) s += pk[n];
        out[OUT_I + b] = s;
    }
}

// ================= launch =================
extern "C" void kernel_launch(void* const* d_in, const int* in_sizes, int n_in,
                              void* d_out, int out_size) {
    const float* Hre = (const float*)d_in[0];
    const float* Him = (const float*)d_in[1];
    const float* P0  = (const float*)d_in[2];
    const float* P1  = (const float*)d_in[3];
    const float* P2  = (const float*)d_in[4];
    const float* w0  = (const float*)d_in[5];
    const float* b0  = (const float*)d_in[6];
    const float* w1  = (const float*)d_in[7];
    const float* b1  = (const float*)d_in[8];
    const float* nz0 = (const float*)d_in[9];
    const float* nz1 = (const float*)d_in[10];
    float* out = (float*)d_out;

    float *Yp, *Y2p;
    __half *A0h, *A0l, *Mh, *Ml;
    cudaGetSymbolAddress((void**)&A0h, g_A0h);
    cudaGetSymbolAddress((void**)&A0l, g_A0l);
    cudaGetSymbolAddress((void**)&Yp,  g_Y);
    cudaGetSymbolAddress((void**)&Mh,  g_Mh);
    cudaGetSymbolAddress((void**)&Ml,  g_Ml);
    cudaGetSymbolAddress((void**)&Y2p, g_Y2);

    cudaFuncSetAttribute(gemm_mma, cudaFuncAttributeMaxDynamicSharedMemorySize, GSMEM);

    // layer 0: K=64
    build_a0<<<BDIM, 256>>>(Hre, Him);
    gemm_mma<<<dim3(8, 2, 64), 256, GSMEM>>>(P0, A0h, A0l, Yp, DIN, CDIM, 1, 1);
    bn_finalize<<<8, 128>>>(w0, b0);
    bn_noise<<<BL, 128>>>(Yp, nz0, 0);

    // layer 1: K=512
    gemm_mma<<<dim3(8, 2, 64), 256, GSMEM>>>(P1, Mh, Ml, Yp, HDIM, CDIM, 1, 1);
    bn_finalize<<<8, 128>>>(w1, b1);
    bn_noise<<<BL, 128>>>(Yp, nz1, 1);

    // layer 2: K=512, M=144 (2 o-tiles, second partially valid)
    gemm_mma<<<dim3(2, 2, 64), 256, GSMEM>>>(P2, Mh, Ml, Y2p, HDIM, MOUT, 0, 0);

    // merged epilogue
    epilogue_kernel<<<BDIM, 128>>>(out);
}